// round 1
// baseline (speedup 1.0000x reference)
#include <cuda_runtime.h>
#include <math.h>

// Problem constants
#define NB 64      // batch
#define NSX 128    // src len
#define NT 128     // trg len
#define NE 128     // embedding dim
#define NH 256     // hidden
#define NV 32000   // vocab out
#define G4 1024    // 4*NH

// ---------------- device scratch (allowed: __device__ globals) ----------------
__device__ float g_x [8192 * NE];    // embedded inputs   (4 MB)
__device__ float g_xg[8192 * G4];    // precomputed x-gates (32 MB)
__device__ float g_ys[8192 * NH];    // per-step layer outputs (8 MB)
__device__ float g_hbuf[2 * NB * NH];
__device__ float g_hF[2 * NB * NH];  // encoder final h (layer 0,1)
__device__ float g_cF[2 * NB * NH];  // encoder final c
__device__ unsigned g_cnt;
__device__ unsigned g_gen;

// ---------------- grid-wide software barrier ----------------
__device__ __forceinline__ void grid_barrier(unsigned nblk) {
    __syncthreads();
    if (threadIdx.x == 0) {
        unsigned gen = atomicAdd(&g_gen, 0u);
        __threadfence();
        unsigned t = atomicAdd(&g_cnt, 1u);
        if (t == nblk - 1u) {
            g_cnt = 0u;
            __threadfence();
            atomicExch(&g_gen, gen + 1u);
        } else {
            while (atomicAdd(&g_gen, 0u) == gen) { }
        }
        __threadfence();
    }
    __syncthreads();
}

// ---------------- embedding kernels ----------------
__global__ void embed_src_kernel(const int* __restrict__ src,
                                 const float* __restrict__ emb,
                                 float* __restrict__ out) {
    int idx = blockIdx.x * blockDim.x + threadIdx.x;     // over NSX*NB*NE
    if (idx >= NSX * NB * NE) return;
    int e = idx % NE;
    int r = idx / NE;           // r = s*NB + b
    int b = r % NB;
    int s = r / NB;
    out[(size_t)r * NE + e] = emb[(size_t)src[b * NSX + s] * NE + e];
}

__global__ void embed_trg_kernel(const int* __restrict__ trg,
                                 const float* __restrict__ emb,
                                 float* __restrict__ out) {
    int idx = blockIdx.x * blockDim.x + threadIdx.x;     // over 127*NB*NE
    if (idx >= 127 * NB * NE) return;
    int e = idx % NE;
    int r = idx / NE;           // r = t*NB + b
    int b = r % NB;
    int t = r / NB;             // 0..126
    int tok = (t == 0) ? 1 : trg[b * NT + t];
    out[(size_t)r * NE + e] = emb[(size_t)tok * NE + e];
}

__global__ void zero_first_kernel(float* __restrict__ out) {
    int idx = blockIdx.x * blockDim.x + threadIdx.x;     // over NB*NV
    if (idx >= NB * NV) return;
    int v = idx % NV;
    int b = idx / NV;
    out[(size_t)b * NT * NV + v] = 0.f;
}

// ---------------- generic fp32 GEMM: C = A[M,K] @ W[N,K]^T + b0 + b1 ----------------
// fcMode: remap output row m = t*64+b -> C[(b*NT + t + 1)*NV + n]
__global__ void gemm_kernel(const float* __restrict__ A, const float* __restrict__ W,
                            const float* __restrict__ b0, const float* __restrict__ b1,
                            float* __restrict__ C, int M, int N, int K, int fcMode) {
    __shared__ float As[8][128];
    __shared__ float Bs[8][128];
    const int n0 = blockIdx.x * 128;
    const int m0 = blockIdx.y * 128;
    const int tid = threadIdx.x;     // 256
    const int tx = tid & 15;
    const int ty = tid >> 4;
    const int lr = tid >> 1;         // 0..127
    const int lk = (tid & 1) * 4;    // 0 or 4

    float acc[8][8];
#pragma unroll
    for (int i = 0; i < 8; i++)
#pragma unroll
        for (int j = 0; j < 8; j++) acc[i][j] = 0.f;

    for (int k0 = 0; k0 < K; k0 += 8) {
        {
            int m = m0 + lr;
            float4 v = make_float4(0.f, 0.f, 0.f, 0.f);
            if (m < M) v = *(const float4*)(A + (size_t)m * K + k0 + lk);
            As[lk + 0][lr] = v.x; As[lk + 1][lr] = v.y;
            As[lk + 2][lr] = v.z; As[lk + 3][lr] = v.w;
        }
        {
            int n = n0 + lr;
            float4 v = *(const float4*)(W + (size_t)n * K + k0 + lk);
            Bs[lk + 0][lr] = v.x; Bs[lk + 1][lr] = v.y;
            Bs[lk + 2][lr] = v.z; Bs[lk + 3][lr] = v.w;
        }
        __syncthreads();
#pragma unroll
        for (int kk = 0; kk < 8; kk++) {
            float4 a0 = *(const float4*)&As[kk][ty * 8];
            float4 a1 = *(const float4*)&As[kk][ty * 8 + 4];
            float4 c0 = *(const float4*)&Bs[kk][tx * 8];
            float4 c1 = *(const float4*)&Bs[kk][tx * 8 + 4];
            float a[8] = {a0.x, a0.y, a0.z, a0.w, a1.x, a1.y, a1.z, a1.w};
            float bb[8] = {c0.x, c0.y, c0.z, c0.w, c1.x, c1.y, c1.z, c1.w};
#pragma unroll
            for (int i = 0; i < 8; i++)
#pragma unroll
                for (int j = 0; j < 8; j++) acc[i][j] += a[i] * bb[j];
        }
        __syncthreads();
    }

    float bias[8];
#pragma unroll
    for (int j = 0; j < 8; j++) {
        int n = n0 + tx * 8 + j;
        float bv = b0 ? b0[n] : 0.f;
        if (b1) bv += b1[n];
        bias[j] = bv;
    }
#pragma unroll
    for (int i = 0; i < 8; i++) {
        int m = m0 + ty * 8 + i;
        if (m >= M) continue;
        if (fcMode) {
            int t = m >> 6;
            int b = m & 63;
            float* crow = C + ((size_t)b * NT + t + 1) * NV;
#pragma unroll
            for (int j = 0; j < 8; j++) crow[n0 + tx * 8 + j] = acc[i][j] + bias[j];
        } else {
            float* crow = C + (size_t)m * N;
#pragma unroll
            for (int j = 0; j < 8; j++) crow[n0 + tx * 8 + j] = acc[i][j] + bias[j];
        }
    }
}

// ---------------- persistent LSTM recurrence ----------------
// grid = 128 blocks = 16 batch-tiles (4 batches each) x 8 n-slices (32 each)
// 256 threads = 8 k-splits x 32 n-lanes
// smem: Wsl[256][129] (k-major, pitch 129: conflict-free on both fill & read)
//       hsh[4][256], red[8*32][17]
#define REC_SMEM_FLOATS (256 * 129 + 4 * 256 + 8 * 32 * 17)
#define REC_SMEM_BYTES  (REC_SMEM_FLOATS * 4)

__global__ void lstm_rec_kernel(const float* __restrict__ xg,   // [nSteps*64, 1024]
                                const float* __restrict__ Whh,  // [1024, 256]
                                const float* __restrict__ hInit,
                                const float* __restrict__ cInit,
                                float* __restrict__ ys,          // nullable [nSteps*64, 256]
                                float* __restrict__ hFin,        // nullable [64,256]
                                float* __restrict__ cFin,        // nullable
                                float* __restrict__ hbuf,        // [2][64][256]
                                int nSteps) {
    extern __shared__ float sm[];
    float* Wsl = sm;                       // 256*129
    float* hsh = Wsl + 256 * 129;          // 4*256
    float* red = hsh + 4 * 256;            // 256*17

    const int tid = threadIdx.x;
    const int bt = blockIdx.x >> 3;        // 0..15
    const int ns = blockIdx.x & 7;         // 0..7
    const int n0 = ns * 32;
    const int ks = tid >> 5;               // 0..7
    const int nl = tid & 31;               // 0..31
    const unsigned nblk = gridDim.x;

    // Fill Whh slice: Wsl[k*129 + g*32+nl] = Whh[g*256 + n0 + nl][k]
    for (int j = 0; j < 128; j++) {
        Wsl[tid * 129 + j] =
            Whh[(size_t)((j >> 5) * 256 + n0 + (j & 31)) * 256 + tid];
    }

    // finalize-thread cell ownership (tid < 128): (fb, fn)
    const int fb = tid >> 5;
    const int fn = tid & 31;
    const int bG = bt * 4 + fb;
    float cS = 0.f;
    if (tid < 128 && cInit) cS = cInit[bG * 256 + n0 + fn];

    // initial h tile (block's 4 contiguous batches)
    {
        float4* dst = (float4*)hsh;  // 256 float4
        if (hInit)
            dst[tid] = ((const float4*)(hInit + (size_t)bt * 4 * 256))[tid];
        else
            dst[tid] = make_float4(0.f, 0.f, 0.f, 0.f);
    }
    __syncthreads();

    int p = 0;
    for (int step = 0; step < nSteps; step++) {
        // ---- partial dot products over this thread's 32-k slice ----
        float part[4][4];
#pragma unroll
        for (int b = 0; b < 4; b++)
#pragma unroll
            for (int g = 0; g < 4; g++) part[b][g] = 0.f;

        const int k0 = ks * 32;
#pragma unroll 8
        for (int kk = 0; kk < 32; kk++) {
            const int k = k0 + kk;
            const float* w = Wsl + k * 129 + nl;
            float w0 = w[0], w1 = w[32], w2 = w[64], w3 = w[96];
#pragma unroll
            for (int b = 0; b < 4; b++) {
                float hv = hsh[b * 256 + k];
                part[b][0] += hv * w0;
                part[b][1] += hv * w1;
                part[b][2] += hv * w2;
                part[b][3] += hv * w3;
            }
        }
        {
            float* rp = red + tid * 17;
#pragma unroll
            for (int b = 0; b < 4; b++)
#pragma unroll
                for (int g = 0; g < 4; g++) rp[b * 4 + g] = part[b][g];
        }
        __syncthreads();

        // ---- finalize: combine partials + x-gates, nonlinearity, state update ----
        if (tid < 128) {
            size_t row = (size_t)step * 64 + bG;
            const float* xr = xg + row * 1024 + n0 + fn;
            float gi = xr[0], gf = xr[256], gg = xr[512], go = xr[768];
#pragma unroll
            for (int q = 0; q < 8; q++) {
                const float* rq = red + (q * 32 + fn) * 17 + fb * 4;
                gi += rq[0]; gf += rq[1]; gg += rq[2]; go += rq[3];
            }
            float iv = 1.f / (1.f + expf(-gi));
            float fv = 1.f / (1.f + expf(-gf));
            float gv = tanhf(gg);
            float ov = 1.f / (1.f + expf(-go));
            cS = fv * cS + iv * gv;
            float h = ov * tanhf(cS);
            hbuf[(size_t)(p ^ 1) * (NB * NH) + bG * 256 + n0 + fn] = h;
            if (ys) ys[row * 256 + n0 + fn] = h;
            if (step == nSteps - 1) {
                if (hFin) hFin[bG * 256 + n0 + fn] = h;
                if (cFin) cFin[bG * 256 + n0 + fn] = cS;
            }
        }

        grid_barrier(nblk);

        // reload h tile for next step
        p ^= 1;
        ((float4*)hsh)[tid] =
            ((const float4*)(hbuf + (size_t)p * (NB * NH) + (size_t)bt * 4 * 256))[tid];
        __syncthreads();
    }
}

// ---------------- host launch ----------------
extern "C" void kernel_launch(void* const* d_in, const int* in_sizes, int n_in,
                              void* d_out, int out_size) {
    const int*   src     = (const int*)d_in[0];
    const int*   trg     = (const int*)d_in[1];
    const float* enc_emb = (const float*)d_in[2];
    const float* dec_emb = (const float*)d_in[3];
    const float* eWih0 = (const float*)d_in[4],  *eWhh0 = (const float*)d_in[5];
    const float* ebih0 = (const float*)d_in[6],  *ebhh0 = (const float*)d_in[7];
    const float* eWih1 = (const float*)d_in[8],  *eWhh1 = (const float*)d_in[9];
    const float* ebih1 = (const float*)d_in[10], *ebhh1 = (const float*)d_in[11];
    const float* dWih0 = (const float*)d_in[12], *dWhh0 = (const float*)d_in[13];
    const float* dbih0 = (const float*)d_in[14], *dbhh0 = (const float*)d_in[15];
    const float* dWih1 = (const float*)d_in[16], *dWhh1 = (const float*)d_in[17];
    const float* dbih1 = (const float*)d_in[18], *dbhh1 = (const float*)d_in[19];
    const float* fcW   = (const float*)d_in[20], *fcb   = (const float*)d_in[21];
    float* out = (float*)d_out;

    float *px, *pxg, *pys, *phbuf, *phF, *pcF;
    cudaGetSymbolAddress((void**)&px,    g_x);
    cudaGetSymbolAddress((void**)&pxg,   g_xg);
    cudaGetSymbolAddress((void**)&pys,   g_ys);
    cudaGetSymbolAddress((void**)&phbuf, g_hbuf);
    cudaGetSymbolAddress((void**)&phF,   g_hF);
    cudaGetSymbolAddress((void**)&pcF,   g_cF);

    cudaFuncSetAttribute(lstm_rec_kernel,
                         cudaFuncAttributeMaxDynamicSharedMemorySize, REC_SMEM_BYTES);

    // ---- Encoder ----
    embed_src_kernel<<<(NSX * NB * NE + 255) / 256, 256>>>(src, enc_emb, px);
    gemm_kernel<<<dim3(G4 / 128, 64), 256>>>(px, eWih0, ebih0, ebhh0, pxg,
                                             8192, G4, NE, 0);
    lstm_rec_kernel<<<128, 256, REC_SMEM_BYTES>>>(pxg, eWhh0, nullptr, nullptr,
                                                  pys, phF, pcF, phbuf, 128);
    gemm_kernel<<<dim3(G4 / 128, 64), 256>>>(pys, eWih1, ebih1, ebhh1, pxg,
                                             8192, G4, NH, 0);
    lstm_rec_kernel<<<128, 256, REC_SMEM_BYTES>>>(pxg, eWhh1, nullptr, nullptr,
                                                  nullptr, phF + NB * NH, pcF + NB * NH,
                                                  phbuf, 128);

    // ---- Decoder (teacher forced) ----
    embed_trg_kernel<<<(127 * NB * NE + 255) / 256, 256>>>(trg, dec_emb, px);
    gemm_kernel<<<dim3(G4 / 128, 64), 256>>>(px, dWih0, dbih0, dbhh0, pxg,
                                             8128, G4, NE, 0);
    lstm_rec_kernel<<<128, 256, REC_SMEM_BYTES>>>(pxg, dWhh0, phF, pcF,
                                                  pys, nullptr, nullptr, phbuf, 127);
    gemm_kernel<<<dim3(G4 / 128, 64), 256>>>(pys, dWih1, dbih1, dbhh1, pxg,
                                             8128, G4, NH, 0);
    lstm_rec_kernel<<<128, 256, REC_SMEM_BYTES>>>(pxg, dWhh1, phF + NB * NH, pcF + NB * NH,
                                                  pys, nullptr, nullptr, phbuf, 127);

    // ---- Output ----
    zero_first_kernel<<<(NB * NV + 255) / 256, 256>>>(out);
    gemm_kernel<<<dim3(NV / 128, 64), 256>>>(pys, fcW, fcb, nullptr, out,
                                             8128, NV, NH, 1);
}

// round 3
// speedup vs baseline: 1.9896x; 1.9896x over previous
#include <cuda_runtime.h>
#include <cuda_fp16.h>
#include <cstdint>
#include <math.h>

// Problem constants
#define NB 64
#define NSX 128
#define NT 128
#define NE 128
#define NH 256
#define NV 32000
#define G4 1024

// ---------------- device scratch ----------------
__device__ float  g_xg[8192 * G4];          // x-gates fp32 (32 MB)
__device__ __half g_xh[8192 * NE];          // fp16 embedded inputs
__device__ __half g_yh[8192 * NH];          // fp16 layer outputs
__device__ float  g_hbuf[2 * NB * NH];
__device__ float  g_hF[2 * NB * NH];
__device__ float  g_cF[2 * NB * NH];
__device__ unsigned g_cnt;
__device__ unsigned g_gen;
__device__ __half g_w0[G4 * NE];            // enc Wih0 fp16
__device__ __half g_w1[G4 * NH];            // enc Wih1
__device__ __half g_w2[G4 * NE];            // dec Wih0
__device__ __half g_w3[G4 * NH];            // dec Wih1
__device__ __half g_fw[NV * NH];            // fc_W fp16

// ---------------- small helpers ----------------
__device__ __forceinline__ uint32_t smem_u32(const void* p) {
    uint32_t a;
    asm("{ .reg .u64 t; cvta.to.shared.u64 t, %1; cvt.u32.u64 %0, t; }"
        : "=r"(a) : "l"(p));
    return a;
}
__device__ __forceinline__ void cp16(uint32_t dst, const void* src) {
    asm volatile("cp.async.cg.shared.global [%0], [%1], 16;" :: "r"(dst), "l"(src));
}
__device__ __forceinline__ void ldsm4(uint32_t& r0, uint32_t& r1, uint32_t& r2,
                                      uint32_t& r3, uint32_t addr) {
    asm volatile("ldmatrix.sync.aligned.m8n8.x4.shared.b16 {%0,%1,%2,%3}, [%4];"
                 : "=r"(r0), "=r"(r1), "=r"(r2), "=r"(r3) : "r"(addr));
}
__device__ __forceinline__ void mma16816(float* c, const uint32_t* a,
                                         uint32_t b0, uint32_t b1) {
    asm volatile(
        "mma.sync.aligned.m16n8k16.row.col.f32.f16.f16.f32 "
        "{%0,%1,%2,%3}, {%4,%5,%6,%7}, {%8,%9}, {%0,%1,%2,%3};"
        : "+f"(c[0]), "+f"(c[1]), "+f"(c[2]), "+f"(c[3])
        : "r"(a[0]), "r"(a[1]), "r"(a[2]), "r"(a[3]), "r"(b0), "r"(b1));
}

// ---------------- grid-wide software barrier ----------------
__device__ __forceinline__ void grid_barrier(unsigned nblk) {
    __syncthreads();
    if (threadIdx.x == 0) {
        unsigned gen = atomicAdd(&g_gen, 0u);
        __threadfence();
        unsigned t = atomicAdd(&g_cnt, 1u);
        if (t == nblk - 1u) {
            g_cnt = 0u;
            __threadfence();
            atomicExch(&g_gen, gen + 1u);
        } else {
            while (atomicAdd(&g_gen, 0u) == gen) { }
        }
        __threadfence();
    }
    __syncthreads();
}

// ---------------- conversion / embedding kernels ----------------
__global__ void f2h_kernel(const float* __restrict__ s, __half* __restrict__ d, int n) {
    int i = blockIdx.x * blockDim.x + threadIdx.x;
    if (i < n) d[i] = __float2half(s[i]);
}

__global__ void embed_src_kernel(const int* __restrict__ src,
                                 const float* __restrict__ emb,
                                 __half* __restrict__ out) {
    int idx = blockIdx.x * blockDim.x + threadIdx.x;
    if (idx >= NSX * NB * NE) return;
    int e = idx % NE;
    int r = idx / NE;
    int b = r % NB;
    int s = r / NB;
    out[(size_t)r * NE + e] = __float2half(emb[(size_t)src[b * NSX + s] * NE + e]);
}

__global__ void embed_trg_kernel(const int* __restrict__ trg,
                                 const float* __restrict__ emb,
                                 __half* __restrict__ out) {
    int idx = blockIdx.x * blockDim.x + threadIdx.x;
    if (idx >= 127 * NB * NE) return;
    int e = idx % NE;
    int r = idx / NE;
    int b = r % NB;
    int t = r / NB;
    int tok = (t == 0) ? 1 : trg[b * NT + t];
    out[(size_t)r * NE + e] = __float2half(emb[(size_t)tok * NE + e]);
}

__global__ void zero_first_kernel(float* __restrict__ out) {
    int idx = blockIdx.x * blockDim.x + threadIdx.x;
    if (idx >= NB * NV) return;
    int v = idx % NV;
    int b = idx / NV;
    out[(size_t)b * NT * NV + v] = 0.f;
}

// ---------------- fp16 tensor-core GEMM ----------------
// C[m,n] = sum_k A[m,k] * W[n,k] + b0[n] (+ b1[n])
// M fixed 8192 (grid.y = 64). Tiles 128x128, BK=64, 3-stage cp.async pipeline.
// fcMode: logical row m = t*64+b -> C[(b*128 + t + 1)*NV + n], skip m >= 8128.
#define GSTAGE 32768
#define GSMEM  (3 * GSTAGE)

__global__ void __launch_bounds__(256)
gemm16_kernel(const __half* __restrict__ A, const __half* __restrict__ W,
              const float* __restrict__ b0, const float* __restrict__ b1,
              float* __restrict__ C, int N, int K, int fcMode) {
    extern __shared__ char smbuf[];
    const uint32_t sb = smem_u32(smbuf);
    const int tid = threadIdx.x;
    const int lane = tid & 31;
    const int wid = tid >> 5;
    const int warp_m = wid & 3;       // 4 warps over M (32 rows each)
    const int warp_n = wid >> 2;      // 2 warps over N (64 cols each)
    const int m0 = blockIdx.y * 128;
    const int n0 = blockIdx.x * 128;
    const int KT = K >> 6;            // 2 or 4

    float acc[2][8][4];
#pragma unroll
    for (int i = 0; i < 2; i++)
#pragma unroll
        for (int j = 0; j < 8; j++)
#pragma unroll
            for (int q = 0; q < 4; q++) acc[i][j][q] = 0.f;

    auto loadStage = [&](int kt, int s) {
        const uint32_t st = sb + (uint32_t)s * GSTAGE;
        const __half* Ag = A + (size_t)m0 * K + kt * 64;
        const __half* Wg = W + (size_t)n0 * K + kt * 64;
#pragma unroll
        for (int i = 0; i < 4; i++) {
            int idx = i * 256 + tid;          // 1024 chunks of 16B
            int row = idx >> 3, c = idx & 7;
            uint32_t off = (uint32_t)(row * 128 + ((c ^ (row & 7)) << 4));
            cp16(st + off, Ag + (size_t)row * K + c * 8);
            cp16(st + 16384 + off, Wg + (size_t)row * K + c * 8);
        }
        asm volatile("cp.async.commit_group;" ::: "memory");
    };

    // prologue (KT >= 2 always)
    loadStage(0, 0);
    loadStage(1, 1);
    asm volatile("cp.async.wait_group 1;" ::: "memory");
    __syncthreads();

    for (int kt = 0; kt < KT; kt++) {
        const int s = kt % 3;
        if (kt + 2 < KT) loadStage(kt + 2, (kt + 2) % 3);
        const uint32_t stA = sb + (uint32_t)s * GSTAGE;
        const uint32_t stB = stA + 16384;
#pragma unroll
        for (int k16 = 0; k16 < 4; k16++) {
            uint32_t a[2][4];
#pragma unroll
            for (int mt = 0; mt < 2; mt++) {
                int row = warp_m * 32 + mt * 16 + (lane & 15);
                int ch = k16 * 2 + (lane >> 4);
                ldsm4(a[mt][0], a[mt][1], a[mt][2], a[mt][3],
                      stA + row * 128 + ((ch ^ (row & 7)) << 4));
            }
#pragma unroll
            for (int p = 0; p < 4; p++) {
                int nrow = warp_n * 64 + p * 16 + ((lane >> 4) & 1) * 8 + (lane & 7);
                int ch = k16 * 2 + ((lane >> 3) & 1);
                uint32_t br0, br1, br2, br3;
                ldsm4(br0, br1, br2, br3,
                      stB + nrow * 128 + ((ch ^ (nrow & 7)) << 4));
#pragma unroll
                for (int mt = 0; mt < 2; mt++) {
                    mma16816(acc[mt][2 * p],     a[mt], br0, br1);
                    mma16816(acc[mt][2 * p + 1], a[mt], br2, br3);
                }
            }
        }
        asm volatile("cp.async.wait_group 1;" ::: "memory");
        __syncthreads();
    }

    // ---- epilogue ----
    const int lrow = lane >> 2;
    const int lcol = (lane & 3) * 2;
#pragma unroll
    for (int nt = 0; nt < 8; nt++) {
        const int n = n0 + warp_n * 64 + nt * 8 + lcol;
        float bv0 = b0 ? b0[n] : 0.f;
        float bv1 = b0 ? b0[n + 1] : 0.f;
        if (b1) { bv0 += b1[n]; bv1 += b1[n + 1]; }
#pragma unroll
        for (int mt = 0; mt < 2; mt++) {
            const int mbase = m0 + warp_m * 32 + mt * 16 + lrow;
#pragma unroll
            for (int half = 0; half < 2; half++) {
                const int m = mbase + half * 8;
                float2 v;
                v.x = acc[mt][nt][half * 2 + 0] + bv0;
                v.y = acc[mt][nt][half * 2 + 1] + bv1;
                if (fcMode) {
                    if (m < 8128) {
                        int t = m >> 6, b = m & 63;
                        *(float2*)(C + ((size_t)(b * 128 + t + 1)) * NV + n) = v;
                    }
                } else {
                    *(float2*)(C + (size_t)m * N + n) = v;
                }
            }
        }
    }
}

// ---------------- persistent LSTM recurrence ----------------
#define REC_SMEM_FLOATS (256 * 129 + 4 * 256 + 8 * 32 * 17)
#define REC_SMEM_BYTES  (REC_SMEM_FLOATS * 4)

__global__ void lstm_rec_kernel(const float* __restrict__ xg,
                                const float* __restrict__ Whh,
                                const float* __restrict__ hInit,
                                const float* __restrict__ cInit,
                                __half* __restrict__ ysh,
                                float* __restrict__ hFin,
                                float* __restrict__ cFin,
                                float* __restrict__ hbuf,
                                int nSteps) {
    extern __shared__ float smf[];
    float* Wsl = smf;
    float* hsh = Wsl + 256 * 129;
    float* red = hsh + 4 * 256;

    const int tid = threadIdx.x;
    const int bt = blockIdx.x >> 3;
    const int ns = blockIdx.x & 7;
    const int n0 = ns * 32;
    const int ks = tid >> 5;
    const int nl = tid & 31;
    const unsigned nblk = gridDim.x;

    for (int j = 0; j < 128; j++) {
        Wsl[tid * 129 + j] =
            Whh[(size_t)((j >> 5) * 256 + n0 + (j & 31)) * 256 + tid];
    }

    const int fb = tid >> 5;
    const int fn = tid & 31;
    const int bG = bt * 4 + fb;
    float cS = 0.f;
    if (tid < 128 && cInit) cS = cInit[bG * 256 + n0 + fn];

    {
        float4* dst = (float4*)hsh;
        if (hInit)
            dst[tid] = ((const float4*)(hInit + (size_t)bt * 4 * 256))[tid];
        else
            dst[tid] = make_float4(0.f, 0.f, 0.f, 0.f);
    }
    __syncthreads();

    int p = 0;
    for (int step = 0; step < nSteps; step++) {
        float part[4][4];
#pragma unroll
        for (int b = 0; b < 4; b++)
#pragma unroll
            for (int g = 0; g < 4; g++) part[b][g] = 0.f;

        const int k0 = ks * 32;
#pragma unroll 8
        for (int kk = 0; kk < 32; kk++) {
            const int k = k0 + kk;
            const float* w = Wsl + k * 129 + nl;
            float w0 = w[0], w1 = w[32], w2 = w[64], w3 = w[96];
#pragma unroll
            for (int b = 0; b < 4; b++) {
                float hv = hsh[b * 256 + k];
                part[b][0] += hv * w0;
                part[b][1] += hv * w1;
                part[b][2] += hv * w2;
                part[b][3] += hv * w3;
            }
        }
        {
            float* rp = red + tid * 17;
#pragma unroll
            for (int b = 0; b < 4; b++)
#pragma unroll
                for (int g = 0; g < 4; g++) rp[b * 4 + g] = part[b][g];
        }
        __syncthreads();

        if (tid < 128) {
            size_t row = (size_t)step * 64 + bG;
            const float* xr = xg + row * 1024 + n0 + fn;
            float gi = xr[0], gf = xr[256], gg = xr[512], go = xr[768];
#pragma unroll
            for (int q = 0; q < 8; q++) {
                const float* rq = red + (q * 32 + fn) * 17 + fb * 4;
                gi += rq[0]; gf += rq[1]; gg += rq[2]; go += rq[3];
            }
            float iv = 1.f / (1.f + expf(-gi));
            float fv = 1.f / (1.f + expf(-gf));
            float gv = tanhf(gg);
            float ov = 1.f / (1.f + expf(-go));
            cS = fv * cS + iv * gv;
            float h = ov * tanhf(cS);
            hbuf[(size_t)(p ^ 1) * (NB * NH) + bG * 256 + n0 + fn] = h;
            if (ysh) ysh[row * 256 + n0 + fn] = __float2half(h);
            if (step == nSteps - 1) {
                if (hFin) hFin[bG * 256 + n0 + fn] = h;
                if (cFin) cFin[bG * 256 + n0 + fn] = cS;
            }
        }

        grid_barrier(nblk);

        p ^= 1;
        ((float4*)hsh)[tid] =
            ((const float4*)(hbuf + (size_t)p * (NB * NH) + (size_t)bt * 4 * 256))[tid];
        __syncthreads();
    }
}

// ---------------- host launch ----------------
extern "C" void kernel_launch(void* const* d_in, const int* in_sizes, int n_in,
                              void* d_out, int out_size) {
    const int*   src     = (const int*)d_in[0];
    const int*   trg     = (const int*)d_in[1];
    const float* enc_emb = (const float*)d_in[2];
    const float* dec_emb = (const float*)d_in[3];
    const float* eWih0 = (const float*)d_in[4],  *eWhh0 = (const float*)d_in[5];
    const float* ebih0 = (const float*)d_in[6],  *ebhh0 = (const float*)d_in[7];
    const float* eWih1 = (const float*)d_in[8],  *eWhh1 = (const float*)d_in[9];
    const float* ebih1 = (const float*)d_in[10], *ebhh1 = (const float*)d_in[11];
    const float* dWih0 = (const float*)d_in[12], *dWhh0 = (const float*)d_in[13];
    const float* dbih0 = (const float*)d_in[14], *dbhh0 = (const float*)d_in[15];
    const float* dWih1 = (const float*)d_in[16], *dWhh1 = (const float*)d_in[17];
    const float* dbih1 = (const float*)d_in[18], *dbhh1 = (const float*)d_in[19];
    const float* fcW   = (const float*)d_in[20], *fcb   = (const float*)d_in[21];
    float* out = (float*)d_out;

    float *pxg, *phbuf, *phF, *pcF;
    __half *pxh, *pyh, *pw0, *pw1, *pw2, *pw3, *pfw;
    cudaGetSymbolAddress((void**)&pxg,   g_xg);
    cudaGetSymbolAddress((void**)&phbuf, g_hbuf);
    cudaGetSymbolAddress((void**)&phF,   g_hF);
    cudaGetSymbolAddress((void**)&pcF,   g_cF);
    cudaGetSymbolAddress((void**)&pxh,   g_xh);
    cudaGetSymbolAddress((void**)&pyh,   g_yh);
    cudaGetSymbolAddress((void**)&pw0,   g_w0);
    cudaGetSymbolAddress((void**)&pw1,   g_w1);
    cudaGetSymbolAddress((void**)&pw2,   g_w2);
    cudaGetSymbolAddress((void**)&pw3,   g_w3);
    cudaGetSymbolAddress((void**)&pfw,   g_fw);

    cudaFuncSetAttribute(lstm_rec_kernel,
                         cudaFuncAttributeMaxDynamicSharedMemorySize, REC_SMEM_BYTES);
    cudaFuncSetAttribute(gemm16_kernel,
                         cudaFuncAttributeMaxDynamicSharedMemorySize, GSMEM);

    // weight conversions (front-loaded)
    f2h_kernel<<<(G4 * NE + 255) / 256, 256>>>(eWih0, pw0, G4 * NE);
    f2h_kernel<<<(G4 * NH + 255) / 256, 256>>>(eWih1, pw1, G4 * NH);
    f2h_kernel<<<(G4 * NE + 255) / 256, 256>>>(dWih0, pw2, G4 * NE);
    f2h_kernel<<<(G4 * NH + 255) / 256, 256>>>(dWih1, pw3, G4 * NH);
    f2h_kernel<<<(NV * NH + 255) / 256, 256>>>(fcW, pfw, NV * NH);

    // ---- Encoder ----
    embed_src_kernel<<<(NSX * NB * NE + 255) / 256, 256>>>(src, enc_emb, pxh);
    gemm16_kernel<<<dim3(8, 64), 256, GSMEM>>>(pxh, pw0, ebih0, ebhh0, pxg,
                                               G4, NE, 0);
    lstm_rec_kernel<<<128, 256, REC_SMEM_BYTES>>>(pxg, eWhh0, nullptr, nullptr,
                                                  pyh, phF, pcF, phbuf, 128);
    gemm16_kernel<<<dim3(8, 64), 256, GSMEM>>>(pyh, pw1, ebih1, ebhh1, pxg,
                                               G4, NH, 0);
    lstm_rec_kernel<<<128, 256, REC_SMEM_BYTES>>>(pxg, eWhh1, nullptr, nullptr,
                                                  nullptr, phF + NB * NH, pcF + NB * NH,
                                                  phbuf, 128);

    // ---- Decoder (teacher forced) ----
    embed_trg_kernel<<<(127 * NB * NE + 255) / 256, 256>>>(trg, dec_emb, pxh);
    gemm16_kernel<<<dim3(8, 64), 256, GSMEM>>>(pxh, pw2, dbih0, dbhh0, pxg,
                                               G4, NE, 0);
    lstm_rec_kernel<<<128, 256, REC_SMEM_BYTES>>>(pxg, dWhh0, phF, pcF,
                                                  pyh, nullptr, nullptr, phbuf, 127);
    gemm16_kernel<<<dim3(8, 64), 256, GSMEM>>>(pyh, pw3, dbih1, dbhh1, pxg,
                                               G4, NH, 0);
    lstm_rec_kernel<<<128, 256, REC_SMEM_BYTES>>>(pxg, dWhh1, phF + NB * NH, pcF + NB * NH,
                                                  pyh, nullptr, nullptr, phbuf, 127);

    // ---- Output: fp16 tensor-core FC over all steps ----
    zero_first_kernel<<<(NB * NV + 255) / 256, 256>>>(out);
    gemm16_kernel<<<dim3(250, 64), 256, GSMEM>>>(pyh, pfw, fcb, nullptr, out,
                                                 NV, NH, 1);
}

// round 4
// speedup vs baseline: 2.0418x; 1.0262x over previous
#include <cuda_runtime.h>
#include <cuda_fp16.h>
#include <cstdint>
#include <math.h>

// Problem constants
#define NB 64
#define NSX 128
#define NT 128
#define NE 128
#define NH 256
#define NV 32000
#define G4 1024

// ---------------- device scratch ----------------
__device__ float  g_xg[8192 * G4];          // x-gates fp32 (32 MB)
__device__ __half g_xh[8192 * NE];          // fp16 embedded inputs
__device__ __half g_yh[8192 * NH];          // fp16 layer outputs
__device__ float  g_hbuf[2 * NB * NH];
__device__ float  g_hF[2 * NB * NH];
__device__ float  g_cF[2 * NB * NH];
__device__ unsigned g_cnt;
__device__ unsigned g_gen;
__device__ __half g_w0[G4 * NE];            // enc Wih0 fp16
__device__ __half g_w1[G4 * NH];            // enc Wih1
__device__ __half g_w2[G4 * NE];            // dec Wih0
__device__ __half g_w3[G4 * NH];            // dec Wih1
__device__ __half g_fw[NV * NH];            // fc_W fp16

// ---------------- small helpers ----------------
__device__ __forceinline__ uint32_t smem_u32(const void* p) {
    uint32_t a;
    asm("{ .reg .u64 t; cvta.to.shared.u64 t, %1; cvt.u32.u64 %0, t; }"
        : "=r"(a) : "l"(p));
    return a;
}
__device__ __forceinline__ void cp16(uint32_t dst, const void* src) {
    asm volatile("cp.async.cg.shared.global [%0], [%1], 16;" :: "r"(dst), "l"(src));
}
__device__ __forceinline__ void ldsm4(uint32_t& r0, uint32_t& r1, uint32_t& r2,
                                      uint32_t& r3, uint32_t addr) {
    asm volatile("ldmatrix.sync.aligned.m8n8.x4.shared.b16 {%0,%1,%2,%3}, [%4];"
                 : "=r"(r0), "=r"(r1), "=r"(r2), "=r"(r3) : "r"(addr));
}
__device__ __forceinline__ void mma16816(float* c, const uint32_t* a,
                                         uint32_t b0, uint32_t b1) {
    asm volatile(
        "mma.sync.aligned.m16n8k16.row.col.f32.f16.f16.f32 "
        "{%0,%1,%2,%3}, {%4,%5,%6,%7}, {%8,%9}, {%0,%1,%2,%3};"
        : "+f"(c[0]), "+f"(c[1]), "+f"(c[2]), "+f"(c[3])
        : "r"(a[0]), "r"(a[1]), "r"(a[2]), "r"(a[3]), "r"(b0), "r"(b1));
}

// ---------------- grid-wide software barrier ----------------
__device__ __forceinline__ void grid_barrier(unsigned nblk) {
    __syncthreads();
    if (threadIdx.x == 0) {
        unsigned gen = atomicAdd(&g_gen, 0u);
        __threadfence();
        unsigned t = atomicAdd(&g_cnt, 1u);
        if (t == nblk - 1u) {
            g_cnt = 0u;
            __threadfence();
            atomicExch(&g_gen, gen + 1u);
        } else {
            while (atomicAdd(&g_gen, 0u) == gen) { }
        }
        __threadfence();
    }
    __syncthreads();
}

// ---------------- conversion / embedding kernels ----------------
__global__ void f2h_kernel(const float* __restrict__ s, __half* __restrict__ d, int n) {
    int i = blockIdx.x * blockDim.x + threadIdx.x;
    if (i < n) d[i] = __float2half(s[i]);
}

__global__ void embed_src_kernel(const int* __restrict__ src,
                                 const float* __restrict__ emb,
                                 __half* __restrict__ out) {
    int idx = blockIdx.x * blockDim.x + threadIdx.x;
    if (idx >= NSX * NB * NE) return;
    int e = idx % NE;
    int r = idx / NE;
    int b = r % NB;
    int s = r / NB;
    out[(size_t)r * NE + e] = __float2half(emb[(size_t)src[b * NSX + s] * NE + e]);
}

__global__ void embed_trg_kernel(const int* __restrict__ trg,
                                 const float* __restrict__ emb,
                                 __half* __restrict__ out) {
    int idx = blockIdx.x * blockDim.x + threadIdx.x;
    if (idx >= 127 * NB * NE) return;
    int e = idx % NE;
    int r = idx / NE;
    int b = r % NB;
    int t = r / NB;
    int tok = (t == 0) ? 1 : trg[b * NT + t];
    out[(size_t)r * NE + e] = __float2half(emb[(size_t)tok * NE + e]);
}

__global__ void zero_first_kernel(float* __restrict__ out) {
    int idx = blockIdx.x * blockDim.x + threadIdx.x;
    if (idx >= NB * NV) return;
    int v = idx % NV;
    int b = idx / NV;
    out[(size_t)b * NT * NV + v] = 0.f;
}

// ---------------- fp16 tensor-core GEMM ----------------
// C[m,n] = sum_k A[m,k] * W[n,k] + b0[n] (+ b1[n])
// M fixed 8192 (grid.y = 64). Tiles 128x128, BK=64, 3-stage cp.async pipeline.
// fcMode: logical row m = t*64+b -> C[(b*128 + t + 1)*NV + n], skip m >= 8128.
#define GSTAGE 32768
#define GSMEM  (3 * GSTAGE)

__global__ void __launch_bounds__(256)
gemm16_kernel(const __half* __restrict__ A, const __half* __restrict__ W,
              const float* __restrict__ b0, const float* __restrict__ b1,
              float* __restrict__ C, int N, int K, int fcMode) {
    extern __shared__ char smbuf[];
    const uint32_t sb = smem_u32(smbuf);
    const int tid = threadIdx.x;
    const int lane = tid & 31;
    const int wid = tid >> 5;
    const int warp_m = wid & 3;       // 4 warps over M (32 rows each)
    const int warp_n = wid >> 2;      // 2 warps over N (64 cols each)
    const int m0 = blockIdx.y * 128;
    const int n0 = blockIdx.x * 128;
    const int KT = K >> 6;            // 2 or 4

    float acc[2][8][4];
#pragma unroll
    for (int i = 0; i < 2; i++)
#pragma unroll
        for (int j = 0; j < 8; j++)
#pragma unroll
            for (int q = 0; q < 4; q++) acc[i][j][q] = 0.f;

    auto loadStage = [&](int kt, int s) {
        const uint32_t st = sb + (uint32_t)s * GSTAGE;
        const __half* Ag = A + (size_t)m0 * K + kt * 64;
        const __half* Wg = W + (size_t)n0 * K + kt * 64;
#pragma unroll
        for (int i = 0; i < 4; i++) {
            int idx = i * 256 + tid;          // 1024 chunks of 16B
            int row = idx >> 3, c = idx & 7;
            uint32_t off = (uint32_t)(row * 128 + ((c ^ (row & 7)) << 4));
            cp16(st + off, Ag + (size_t)row * K + c * 8);
            cp16(st + 16384 + off, Wg + (size_t)row * K + c * 8);
        }
        asm volatile("cp.async.commit_group;" ::: "memory");
    };

    // prologue (KT >= 2 always)
    loadStage(0, 0);
    loadStage(1, 1);
    asm volatile("cp.async.wait_group 1;" ::: "memory");
    __syncthreads();

    for (int kt = 0; kt < KT; kt++) {
        const int s = kt % 3;
        if (kt + 2 < KT) loadStage(kt + 2, (kt + 2) % 3);
        const uint32_t stA = sb + (uint32_t)s * GSTAGE;
        const uint32_t stB = stA + 16384;
#pragma unroll
        for (int k16 = 0; k16 < 4; k16++) {
            uint32_t a[2][4];
#pragma unroll
            for (int mt = 0; mt < 2; mt++) {
                int row = warp_m * 32 + mt * 16 + (lane & 15);
                int ch = k16 * 2 + (lane >> 4);
                ldsm4(a[mt][0], a[mt][1], a[mt][2], a[mt][3],
                      stA + row * 128 + ((ch ^ (row & 7)) << 4));
            }
#pragma unroll
            for (int p = 0; p < 4; p++) {
                int nrow = warp_n * 64 + p * 16 + ((lane >> 4) & 1) * 8 + (lane & 7);
                int ch = k16 * 2 + ((lane >> 3) & 1);
                uint32_t br0, br1, br2, br3;
                ldsm4(br0, br1, br2, br3,
                      stB + nrow * 128 + ((ch ^ (nrow & 7)) << 4));
#pragma unroll
                for (int mt = 0; mt < 2; mt++) {
                    mma16816(acc[mt][2 * p],     a[mt], br0, br1);
                    mma16816(acc[mt][2 * p + 1], a[mt], br2, br3);
                }
            }
        }
        asm volatile("cp.async.wait_group 1;" ::: "memory");
        __syncthreads();
    }

    // ---- epilogue ----
    const int lrow = lane >> 2;
    const int lcol = (lane & 3) * 2;
#pragma unroll
    for (int nt = 0; nt < 8; nt++) {
        const int n = n0 + warp_n * 64 + nt * 8 + lcol;
        float bv0 = b0 ? b0[n] : 0.f;
        float bv1 = b0 ? b0[n + 1] : 0.f;
        if (b1) { bv0 += b1[n]; bv1 += b1[n + 1]; }
#pragma unroll
        for (int mt = 0; mt < 2; mt++) {
            const int mbase = m0 + warp_m * 32 + mt * 16 + lrow;
#pragma unroll
            for (int half = 0; half < 2; half++) {
                const int m = mbase + half * 8;
                float2 v;
                v.x = acc[mt][nt][half * 2 + 0] + bv0;
                v.y = acc[mt][nt][half * 2 + 1] + bv1;
                if (fcMode) {
                    if (m < 8128) {
                        int t = m >> 6, b = m & 63;
                        *(float2*)(C + ((size_t)(b * 128 + t + 1)) * NV + n) = v;
                    }
                } else {
                    *(float2*)(C + (size_t)m * N + n) = v;
                }
            }
        }
    }
}

// ---------------- persistent LSTM recurrence ----------------
#define REC_SMEM_FLOATS (256 * 129 + 4 * 256 + 8 * 32 * 17)
#define REC_SMEM_BYTES  (REC_SMEM_FLOATS * 4)

__global__ void lstm_rec_kernel(const float* __restrict__ xg,
                                const float* __restrict__ Whh,
                                const float* __restrict__ hInit,
                                const float* __restrict__ cInit,
                                __half* __restrict__ ysh,
                                float* __restrict__ hFin,
                                float* __restrict__ cFin,
                                float* __restrict__ hbuf,
                                int nSteps) {
    extern __shared__ float smf[];
    float* Wsl = smf;
    float* hsh = Wsl + 256 * 129;
    float* red = hsh + 4 * 256;

    const int tid = threadIdx.x;
    const int bt = blockIdx.x >> 3;
    const int ns = blockIdx.x & 7;
    const int n0 = ns * 32;
    const int ks = tid >> 5;
    const int nl = tid & 31;
    const unsigned nblk = gridDim.x;

    for (int j = 0; j < 128; j++) {
        Wsl[tid * 129 + j] =
            Whh[(size_t)((j >> 5) * 256 + n0 + (j & 31)) * 256 + tid];
    }

    const int fb = tid >> 5;
    const int fn = tid & 31;
    const int bG = bt * 4 + fb;
    float cS = 0.f;
    if (tid < 128 && cInit) cS = cInit[bG * 256 + n0 + fn];

    {
        float4* dst = (float4*)hsh;
        if (hInit)
            dst[tid] = ((const float4*)(hInit + (size_t)bt * 4 * 256))[tid];
        else
            dst[tid] = make_float4(0.f, 0.f, 0.f, 0.f);
    }
    __syncthreads();

    int p = 0;
    for (int step = 0; step < nSteps; step++) {
        float part[4][4];
#pragma unroll
        for (int b = 0; b < 4; b++)
#pragma unroll
            for (int g = 0; g < 4; g++) part[b][g] = 0.f;

        const int k0 = ks * 32;
#pragma unroll 8
        for (int kk = 0; kk < 32; kk++) {
            const int k = k0 + kk;
            const float* w = Wsl + k * 129 + nl;
            float w0 = w[0], w1 = w[32], w2 = w[64], w3 = w[96];
#pragma unroll
            for (int b = 0; b < 4; b++) {
                float hv = hsh[b * 256 + k];
                part[b][0] += hv * w0;
                part[b][1] += hv * w1;
                part[b][2] += hv * w2;
                part[b][3] += hv * w3;
            }
        }
        {
            float* rp = red + tid * 17;
#pragma unroll
            for (int b = 0; b < 4; b++)
#pragma unroll
                for (int g = 0; g < 4; g++) rp[b * 4 + g] = part[b][g];
        }
        __syncthreads();

        if (tid < 128) {
            size_t row = (size_t)step * 64 + bG;
            const float* xr = xg + row * 1024 + n0 + fn;
            float gi = xr[0], gf = xr[256], gg = xr[512], go = xr[768];
#pragma unroll
            for (int q = 0; q < 8; q++) {
                const float* rq = red + (q * 32 + fn) * 17 + fb * 4;
                gi += rq[0]; gf += rq[1]; gg += rq[2]; go += rq[3];
            }
            float iv = 1.f / (1.f + expf(-gi));
            float fv = 1.f / (1.f + expf(-gf));
            float gv = tanhf(gg);
            float ov = 1.f / (1.f + expf(-go));
            cS = fv * cS + iv * gv;
            float h = ov * tanhf(cS);
            hbuf[(size_t)(p ^ 1) * (NB * NH) + bG * 256 + n0 + fn] = h;
            if (ysh) ysh[row * 256 + n0 + fn] = __float2half(h);
            if (step == nSteps - 1) {
                if (hFin) hFin[bG * 256 + n0 + fn] = h;
                if (cFin) cFin[bG * 256 + n0 + fn] = cS;
            }
        }

        grid_barrier(nblk);

        p ^= 1;
        ((float4*)hsh)[tid] =
            ((const float4*)(hbuf + (size_t)p * (NB * NH) + (size_t)bt * 4 * 256))[tid];
        __syncthreads();
    }
}

// ---------------- host launch ----------------
extern "C" void kernel_launch(void* const* d_in, const int* in_sizes, int n_in,
                              void* d_out, int out_size) {
    const int*   src     = (const int*)d_in[0];
    const int*   trg     = (const int*)d_in[1];
    const float* enc_emb = (const float*)d_in[2];
    const float* dec_emb = (const float*)d_in[3];
    const float* eWih0 = (const float*)d_in[4],  *eWhh0 = (const float*)d_in[5];
    const float* ebih0 = (const float*)d_in[6],  *ebhh0 = (const float*)d_in[7];
    const float* eWih1 = (const float*)d_in[8],  *eWhh1 = (const float*)d_in[9];
    const float* ebih1 = (const float*)d_in[10], *ebhh1 = (const float*)d_in[11];
    const float* dWih0 = (const float*)d_in[12], *dWhh0 = (const float*)d_in[13];
    const float* dbih0 = (const float*)d_in[14], *dbhh0 = (const float*)d_in[15];
    const float* dWih1 = (const float*)d_in[16], *dWhh1 = (const float*)d_in[17];
    const float* dbih1 = (const float*)d_in[18], *dbhh1 = (const float*)d_in[19];
    const float* fcW   = (const float*)d_in[20], *fcb   = (const float*)d_in[21];
    float* out = (float*)d_out;

    float *pxg, *phbuf, *phF, *pcF;
    __half *pxh, *pyh, *pw0, *pw1, *pw2, *pw3, *pfw;
    cudaGetSymbolAddress((void**)&pxg,   g_xg);
    cudaGetSymbolAddress((void**)&phbuf, g_hbuf);
    cudaGetSymbolAddress((void**)&phF,   g_hF);
    cudaGetSymbolAddress((void**)&pcF,   g_cF);
    cudaGetSymbolAddress((void**)&pxh,   g_xh);
    cudaGetSymbolAddress((void**)&pyh,   g_yh);
    cudaGetSymbolAddress((void**)&pw0,   g_w0);
    cudaGetSymbolAddress((void**)&pw1,   g_w1);
    cudaGetSymbolAddress((void**)&pw2,   g_w2);
    cudaGetSymbolAddress((void**)&pw3,   g_w3);
    cudaGetSymbolAddress((void**)&pfw,   g_fw);

    cudaFuncSetAttribute(lstm_rec_kernel,
                         cudaFuncAttributeMaxDynamicSharedMemorySize, REC_SMEM_BYTES);
    cudaFuncSetAttribute(gemm16_kernel,
                         cudaFuncAttributeMaxDynamicSharedMemorySize, GSMEM);

    // weight conversions (front-loaded)
    f2h_kernel<<<(G4 * NE + 255) / 256, 256>>>(eWih0, pw0, G4 * NE);
    f2h_kernel<<<(G4 * NH + 255) / 256, 256>>>(eWih1, pw1, G4 * NH);
    f2h_kernel<<<(G4 * NE + 255) / 256, 256>>>(dWih0, pw2, G4 * NE);
    f2h_kernel<<<(G4 * NH + 255) / 256, 256>>>(dWih1, pw3, G4 * NH);
    f2h_kernel<<<(NV * NH + 255) / 256, 256>>>(fcW, pfw, NV * NH);

    // ---- Encoder ----
    embed_src_kernel<<<(NSX * NB * NE + 255) / 256, 256>>>(src, enc_emb, pxh);
    gemm16_kernel<<<dim3(8, 64), 256, GSMEM>>>(pxh, pw0, ebih0, ebhh0, pxg,
                                               G4, NE, 0);
    lstm_rec_kernel<<<128, 256, REC_SMEM_BYTES>>>(pxg, eWhh0, nullptr, nullptr,
                                                  pyh, phF, pcF, phbuf, 128);
    gemm16_kernel<<<dim3(8, 64), 256, GSMEM>>>(pyh, pw1, ebih1, ebhh1, pxg,
                                               G4, NH, 0);
    lstm_rec_kernel<<<128, 256, REC_SMEM_BYTES>>>(pxg, eWhh1, nullptr, nullptr,
                                                  nullptr, phF + NB * NH, pcF + NB * NH,
                                                  phbuf, 128);

    // ---- Decoder (teacher forced) ----
    embed_trg_kernel<<<(127 * NB * NE + 255) / 256, 256>>>(trg, dec_emb, pxh);
    gemm16_kernel<<<dim3(8, 64), 256, GSMEM>>>(pxh, pw2, dbih0, dbhh0, pxg,
                                               G4, NE, 0);
    lstm_rec_kernel<<<128, 256, REC_SMEM_BYTES>>>(pxg, dWhh0, phF, pcF,
                                                  pyh, nullptr, nullptr, phbuf, 127);
    gemm16_kernel<<<dim3(8, 64), 256, GSMEM>>>(pyh, pw3, dbih1, dbhh1, pxg,
                                               G4, NH, 0);
    lstm_rec_kernel<<<128, 256, REC_SMEM_BYTES>>>(pxg, dWhh1, phF + NB * NH, pcF + NB * NH,
                                                  pyh, nullptr, nullptr, phbuf, 127);

    // ---- Output: fp16 tensor-core FC over all steps ----
    zero_first_kernel<<<(NB * NV + 255) / 256, 256>>>(out);
    gemm16_kernel<<<dim3(250, 64), 256, GSMEM>>>(pyh, pfw, fcb, nullptr, out,
                                                 NV, NH, 1);
}

// round 5
// speedup vs baseline: 2.1641x; 1.0599x over previous
#include <cuda_runtime.h>
#include <cuda_fp16.h>
#include <cstdint>
#include <math.h>

// Problem constants
#define NB 64
#define NSX 128
#define NT 128
#define NE 128
#define NH 256
#define NV 32000
#define G4 1024

// ---------------- device scratch ----------------
__device__ float  g_xg[8192 * G4];          // x-gates fp32 (32 MB)
__device__ __half g_xh[8192 * NE];          // fp16 embedded inputs
__device__ __half g_yh[8192 * NH];          // fp16 layer outputs
__device__ float  g_hF[2 * NB * NH];
__device__ float  g_cF[2 * NB * NH];
__device__ __half g_w0[G4 * NE];            // enc Wih0 fp16
__device__ __half g_w1[G4 * NH];            // enc Wih1
__device__ __half g_w2[G4 * NE];            // dec Wih0
__device__ __half g_w3[G4 * NH];            // dec Wih1
__device__ __half g_fw[NV * NH];            // fc_W fp16

// ---------------- small helpers ----------------
__device__ __forceinline__ uint32_t smem_u32(const void* p) {
    uint32_t a;
    asm("{ .reg .u64 t; cvta.to.shared.u64 t, %1; cvt.u32.u64 %0, t; }"
        : "=r"(a) : "l"(p));
    return a;
}
__device__ __forceinline__ void cp16(uint32_t dst, const void* src) {
    asm volatile("cp.async.cg.shared.global [%0], [%1], 16;" :: "r"(dst), "l"(src));
}
__device__ __forceinline__ void ldsm4(uint32_t& r0, uint32_t& r1, uint32_t& r2,
                                      uint32_t& r3, uint32_t addr) {
    asm volatile("ldmatrix.sync.aligned.m8n8.x4.shared.b16 {%0,%1,%2,%3}, [%4];"
                 : "=r"(r0), "=r"(r1), "=r"(r2), "=r"(r3) : "r"(addr));
}
__device__ __forceinline__ void mma16816(float* c, const uint32_t* a,
                                         uint32_t b0, uint32_t b1) {
    asm volatile(
        "mma.sync.aligned.m16n8k16.row.col.f32.f16.f16.f32 "
        "{%0,%1,%2,%3}, {%4,%5,%6,%7}, {%8,%9}, {%0,%1,%2,%3};"
        : "+f"(c[0]), "+f"(c[1]), "+f"(c[2]), "+f"(c[3])
        : "r"(a[0]), "r"(a[1]), "r"(a[2]), "r"(a[3]), "r"(b0), "r"(b1));
}
#define CLUSTER_SYNC() do { \
    asm volatile("barrier.cluster.arrive.aligned;" ::: "memory"); \
    asm volatile("barrier.cluster.wait.aligned;" ::: "memory"); \
} while (0)

// ---------------- conversion / embedding kernels ----------------
__global__ void f2h_kernel(const float* __restrict__ s, __half* __restrict__ d, int n) {
    int i = blockIdx.x * blockDim.x + threadIdx.x;
    if (i < n) d[i] = __float2half(s[i]);
}

__global__ void embed_src_kernel(const int* __restrict__ src,
                                 const float* __restrict__ emb,
                                 __half* __restrict__ out) {
    int idx = blockIdx.x * blockDim.x + threadIdx.x;
    if (idx >= NSX * NB * NE) return;
    int e = idx % NE;
    int r = idx / NE;
    int b = r % NB;
    int s = r / NB;
    out[(size_t)r * NE + e] = __float2half(emb[(size_t)src[b * NSX + s] * NE + e]);
}

__global__ void embed_trg_kernel(const int* __restrict__ trg,
                                 const float* __restrict__ emb,
                                 __half* __restrict__ out) {
    int idx = blockIdx.x * blockDim.x + threadIdx.x;
    if (idx >= 127 * NB * NE) return;
    int e = idx % NE;
    int r = idx / NE;
    int b = r % NB;
    int t = r / NB;
    int tok = (t == 0) ? 1 : trg[b * NT + t];
    out[(size_t)r * NE + e] = __float2half(emb[(size_t)tok * NE + e]);
}

__global__ void zero_first_kernel(float* __restrict__ out) {
    int idx = blockIdx.x * blockDim.x + threadIdx.x;
    if (idx >= NB * NV) return;
    int v = idx % NV;
    int b = idx / NV;
    out[(size_t)b * NT * NV + v] = 0.f;
}

// ---------------- fp16 tensor-core GEMM ----------------
#define GSTAGE 32768
#define GSMEM  (3 * GSTAGE)

__global__ void __launch_bounds__(256)
gemm16_kernel(const __half* __restrict__ A, const __half* __restrict__ W,
              const float* __restrict__ b0, const float* __restrict__ b1,
              float* __restrict__ C, int N, int K, int fcMode) {
    extern __shared__ char smbuf[];
    const uint32_t sb = smem_u32(smbuf);
    const int tid = threadIdx.x;
    const int lane = tid & 31;
    const int wid = tid >> 5;
    const int warp_m = wid & 3;
    const int warp_n = wid >> 2;
    const int m0 = blockIdx.y * 128;
    const int n0 = blockIdx.x * 128;
    const int KT = K >> 6;

    float acc[2][8][4];
#pragma unroll
    for (int i = 0; i < 2; i++)
#pragma unroll
        for (int j = 0; j < 8; j++)
#pragma unroll
            for (int q = 0; q < 4; q++) acc[i][j][q] = 0.f;

    auto loadStage = [&](int kt, int s) {
        const uint32_t st = sb + (uint32_t)s * GSTAGE;
        const __half* Ag = A + (size_t)m0 * K + kt * 64;
        const __half* Wg = W + (size_t)n0 * K + kt * 64;
#pragma unroll
        for (int i = 0; i < 4; i++) {
            int idx = i * 256 + tid;
            int row = idx >> 3, c = idx & 7;
            uint32_t off = (uint32_t)(row * 128 + ((c ^ (row & 7)) << 4));
            cp16(st + off, Ag + (size_t)row * K + c * 8);
            cp16(st + 16384 + off, Wg + (size_t)row * K + c * 8);
        }
        asm volatile("cp.async.commit_group;" ::: "memory");
    };

    loadStage(0, 0);
    loadStage(1, 1);
    asm volatile("cp.async.wait_group 1;" ::: "memory");
    __syncthreads();

    for (int kt = 0; kt < KT; kt++) {
        const int s = kt % 3;
        if (kt + 2 < KT) loadStage(kt + 2, (kt + 2) % 3);
        const uint32_t stA = sb + (uint32_t)s * GSTAGE;
        const uint32_t stB = stA + 16384;
#pragma unroll
        for (int k16 = 0; k16 < 4; k16++) {
            uint32_t a[2][4];
#pragma unroll
            for (int mt = 0; mt < 2; mt++) {
                int row = warp_m * 32 + mt * 16 + (lane & 15);
                int ch = k16 * 2 + (lane >> 4);
                ldsm4(a[mt][0], a[mt][1], a[mt][2], a[mt][3],
                      stA + row * 128 + ((ch ^ (row & 7)) << 4));
            }
#pragma unroll
            for (int p = 0; p < 4; p++) {
                int nrow = warp_n * 64 + p * 16 + ((lane >> 4) & 1) * 8 + (lane & 7);
                int ch = k16 * 2 + ((lane >> 3) & 1);
                uint32_t br0, br1, br2, br3;
                ldsm4(br0, br1, br2, br3,
                      stB + nrow * 128 + ((ch ^ (nrow & 7)) << 4));
#pragma unroll
                for (int mt = 0; mt < 2; mt++) {
                    mma16816(acc[mt][2 * p],     a[mt], br0, br1);
                    mma16816(acc[mt][2 * p + 1], a[mt], br2, br3);
                }
            }
        }
        asm volatile("cp.async.wait_group 1;" ::: "memory");
        __syncthreads();
    }

    const int lrow = lane >> 2;
    const int lcol = (lane & 3) * 2;
#pragma unroll
    for (int nt = 0; nt < 8; nt++) {
        const int n = n0 + warp_n * 64 + nt * 8 + lcol;
        float bv0 = b0 ? b0[n] : 0.f;
        float bv1 = b0 ? b0[n + 1] : 0.f;
        if (b1) { bv0 += b1[n]; bv1 += b1[n + 1]; }
#pragma unroll
        for (int mt = 0; mt < 2; mt++) {
            const int mbase = m0 + warp_m * 32 + mt * 16 + lrow;
#pragma unroll
            for (int half = 0; half < 2; half++) {
                const int m = mbase + half * 8;
                float2 v;
                v.x = acc[mt][nt][half * 2 + 0] + bv0;
                v.y = acc[mt][nt][half * 2 + 1] + bv1;
                if (fcMode) {
                    if (m < 8128) {
                        int t = m >> 6, b = m & 63;
                        *(float2*)(C + ((size_t)(b * 128 + t + 1)) * NV + n) = v;
                    }
                } else {
                    *(float2*)(C + (size_t)m * N + n) = v;
                }
            }
        }
    }
}

// ---------------- clustered persistent LSTM recurrence ----------------
// 16 clusters x 8 CTAs. Cluster owns 4 batches; CTA rank = n-slice (32 gate cols
// per gate block). h broadcast via DSMEM into double-buffered smem; cluster.sync
// replaces the old global-atomic grid barrier + gmem h round-trip.
#define REC_SMEM_FLOATS (256 * 129 + 2 * 1024 + 8 * 32 * 17)
#define REC_SMEM_BYTES  (REC_SMEM_FLOATS * 4)

__global__ void __cluster_dims__(8, 1, 1) __launch_bounds__(256, 1)
lstm_rec_kernel(const float* __restrict__ xg,
                const float* __restrict__ Whh,
                const float* __restrict__ hInit,
                const float* __restrict__ cInit,
                __half* __restrict__ ysh,
                float* __restrict__ hFin,
                float* __restrict__ cFin,
                int nSteps) {
    extern __shared__ float smf[];
    float* Wsl = smf;                      // 256*129
    float* hs0 = Wsl + 256 * 129;          // 1024 (buffer 0)
    float* hs1 = hs0 + 1024;               // 1024 (buffer 1)
    float* red = hs1 + 1024;               // 256*17

    const int tid = threadIdx.x;
    uint32_t rank;
    asm("mov.u32 %0, %%cluster_ctarank;" : "=r"(rank));
    const int bt = blockIdx.x >> 3;        // cluster id (4 batches)
    const int n0 = (int)rank * 32;
    const int ks = tid >> 5;
    const int nl = tid & 31;

    // fill Whh slice: Wsl[k*129 + g*32+nl] = Whh[g*256 + n0 + (j&31)][k]
    for (int j = 0; j < 128; j++) {
        Wsl[tid * 129 + j] =
            Whh[(size_t)((j >> 5) * 256 + n0 + (j & 31)) * 256 + tid];
    }

    const int fb = tid >> 5;               // finalize: batch-in-cluster (tid<128)
    const int fn = tid & 31;
    const int bG = bt * 4 + fb;
    float cS = 0.f;
    if (tid < 128 && cInit) cS = cInit[bG * 256 + n0 + fn];

    // init h buffer 0 (each CTA loads its cluster's 4 batches locally)
    if (hInit)
        ((float4*)hs0)[tid] = ((const float4*)(hInit + (size_t)bt * 4 * 256))[tid];
    else
        ((float4*)hs0)[tid] = make_float4(0.f, 0.f, 0.f, 0.f);

    // precompute remote DSMEM addresses of this thread's h slot (both buffers)
    uint32_t remA[8], remB[8];
    if (tid < 128) {
        uint32_t offs = (uint32_t)(fb * 256 + n0 + fn) * 4;
        uint32_t la = smem_u32(hs0) + offs;
        uint32_t lb = smem_u32(hs1) + offs;
#pragma unroll
        for (int r = 0; r < 8; r++) {
            asm("mapa.shared::cluster.u32 %0, %1, %2;" : "=r"(remA[r]) : "r"(la), "r"(r));
            asm("mapa.shared::cluster.u32 %0, %1, %2;" : "=r"(remB[r]) : "r"(lb), "r"(r));
        }
    }
    __syncthreads();
    CLUSTER_SYNC();

    int p = 0;
    for (int step = 0; step < nSteps; step++) {
        const float* hcur = p ? hs1 : hs0;

        // ---- partial dot products over this thread's 32-k slice ----
        float part[4][4];
#pragma unroll
        for (int b = 0; b < 4; b++)
#pragma unroll
            for (int g = 0; g < 4; g++) part[b][g] = 0.f;

        const int k0 = ks * 32;
#pragma unroll 8
        for (int kk = 0; kk < 32; kk++) {
            const int k = k0 + kk;
            const float* w = Wsl + k * 129 + nl;
            float w0 = w[0], w1 = w[32], w2 = w[64], w3 = w[96];
#pragma unroll
            for (int b = 0; b < 4; b++) {
                float hv = hcur[b * 256 + k];
                part[b][0] += hv * w0;
                part[b][1] += hv * w1;
                part[b][2] += hv * w2;
                part[b][3] += hv * w3;
            }
        }
        {
            float* rp = red + tid * 17;
#pragma unroll
            for (int b = 0; b < 4; b++)
#pragma unroll
                for (int g = 0; g < 4; g++) rp[b * 4 + g] = part[b][g];
        }
        __syncthreads();

        // ---- finalize + DSMEM broadcast ----
        if (tid < 128) {
            size_t row = (size_t)step * 64 + bG;
            const float* xr = xg + row * 1024 + n0 + fn;
            float gi = xr[0], gf = xr[256], gg = xr[512], go = xr[768];
#pragma unroll
            for (int q = 0; q < 8; q++) {
                const float* rq = red + (q * 32 + fn) * 17 + fb * 4;
                gi += rq[0]; gf += rq[1]; gg += rq[2]; go += rq[3];
            }
            float iv = 1.f / (1.f + expf(-gi));
            float fv = 1.f / (1.f + expf(-gf));
            float gv = tanhf(gg);
            float ov = 1.f / (1.f + expf(-go));
            cS = fv * cS + iv * gv;
            float h = ov * tanhf(cS);

            uint32_t hb = __float_as_uint(h);
#pragma unroll
            for (int r = 0; r < 8; r++) {
                uint32_t ra = p ? remA[r] : remB[r];   // write buffer p^1
                asm volatile("st.shared::cluster.u32 [%0], %1;" :: "r"(ra), "r"(hb));
            }
            if (ysh) ysh[row * 256 + n0 + fn] = __float2half(h);
            if (step == nSteps - 1) {
                if (hFin) hFin[bG * 256 + n0 + fn] = h;
                if (cFin) cFin[bG * 256 + n0 + fn] = cS;
            }
        }

        CLUSTER_SYNC();
        p ^= 1;
    }
}

// ---------------- host launch ----------------
extern "C" void kernel_launch(void* const* d_in, const int* in_sizes, int n_in,
                              void* d_out, int out_size) {
    const int*   src     = (const int*)d_in[0];
    const int*   trg     = (const int*)d_in[1];
    const float* enc_emb = (const float*)d_in[2];
    const float* dec_emb = (const float*)d_in[3];
    const float* eWih0 = (const float*)d_in[4],  *eWhh0 = (const float*)d_in[5];
    const float* ebih0 = (const float*)d_in[6],  *ebhh0 = (const float*)d_in[7];
    const float* eWih1 = (const float*)d_in[8],  *eWhh1 = (const float*)d_in[9];
    const float* ebih1 = (const float*)d_in[10], *ebhh1 = (const float*)d_in[11];
    const float* dWih0 = (const float*)d_in[12], *dWhh0 = (const float*)d_in[13];
    const float* dbih0 = (const float*)d_in[14], *dbhh0 = (const float*)d_in[15];
    const float* dWih1 = (const float*)d_in[16], *dWhh1 = (const float*)d_in[17];
    const float* dbih1 = (const float*)d_in[18], *dbhh1 = (const float*)d_in[19];
    const float* fcW   = (const float*)d_in[20], *fcb   = (const float*)d_in[21];
    float* out = (float*)d_out;

    float *pxg, *phF, *pcF;
    __half *pxh, *pyh, *pw0, *pw1, *pw2, *pw3, *pfw;
    cudaGetSymbolAddress((void**)&pxg,   g_xg);
    cudaGetSymbolAddress((void**)&phF,   g_hF);
    cudaGetSymbolAddress((void**)&pcF,   g_cF);
    cudaGetSymbolAddress((void**)&pxh,   g_xh);
    cudaGetSymbolAddress((void**)&pyh,   g_yh);
    cudaGetSymbolAddress((void**)&pw0,   g_w0);
    cudaGetSymbolAddress((void**)&pw1,   g_w1);
    cudaGetSymbolAddress((void**)&pw2,   g_w2);
    cudaGetSymbolAddress((void**)&pw3,   g_w3);
    cudaGetSymbolAddress((void**)&pfw,   g_fw);

    cudaFuncSetAttribute(lstm_rec_kernel,
                         cudaFuncAttributeMaxDynamicSharedMemorySize, REC_SMEM_BYTES);
    cudaFuncSetAttribute(gemm16_kernel,
                         cudaFuncAttributeMaxDynamicSharedMemorySize, GSMEM);

    // weight conversions (front-loaded)
    f2h_kernel<<<(G4 * NE + 255) / 256, 256>>>(eWih0, pw0, G4 * NE);
    f2h_kernel<<<(G4 * NH + 255) / 256, 256>>>(eWih1, pw1, G4 * NH);
    f2h_kernel<<<(G4 * NE + 255) / 256, 256>>>(dWih0, pw2, G4 * NE);
    f2h_kernel<<<(G4 * NH + 255) / 256, 256>>>(dWih1, pw3, G4 * NH);
    f2h_kernel<<<(NV * NH + 255) / 256, 256>>>(fcW, pfw, NV * NH);

    // ---- Encoder ----
    embed_src_kernel<<<(NSX * NB * NE + 255) / 256, 256>>>(src, enc_emb, pxh);
    gemm16_kernel<<<dim3(8, 64), 256, GSMEM>>>(pxh, pw0, ebih0, ebhh0, pxg,
                                               G4, NE, 0);
    lstm_rec_kernel<<<128, 256, REC_SMEM_BYTES>>>(pxg, eWhh0, nullptr, nullptr,
                                                  pyh, phF, pcF, 128);
    gemm16_kernel<<<dim3(8, 64), 256, GSMEM>>>(pyh, pw1, ebih1, ebhh1, pxg,
                                               G4, NH, 0);
    lstm_rec_kernel<<<128, 256, REC_SMEM_BYTES>>>(pxg, eWhh1, nullptr, nullptr,
                                                  nullptr, phF + NB * NH, pcF + NB * NH,
                                                  128);

    // ---- Decoder (teacher forced) ----
    embed_trg_kernel<<<(127 * NB * NE + 255) / 256, 256>>>(trg, dec_emb, pxh);
    gemm16_kernel<<<dim3(8, 64), 256, GSMEM>>>(pxh, pw2, dbih0, dbhh0, pxg,
                                               G4, NE, 0);
    lstm_rec_kernel<<<128, 256, REC_SMEM_BYTES>>>(pxg, dWhh0, phF, pcF,
                                                  pyh, nullptr, nullptr, 127);
    gemm16_kernel<<<dim3(8, 64), 256, GSMEM>>>(pyh, pw3, dbih1, dbhh1, pxg,
                                               G4, NH, 0);
    lstm_rec_kernel<<<128, 256, REC_SMEM_BYTES>>>(pxg, dWhh1, phF + NB * NH, pcF + NB * NH,
                                                  pyh, nullptr, nullptr, 127);

    // ---- Output: fp16 tensor-core FC over all steps ----
    zero_first_kernel<<<(NB * NV + 255) / 256, 256>>>(out);
    gemm16_kernel<<<dim3(250, 64), 256, GSMEM>>>(pyh, pfw, fcb, nullptr, out,
                                                 NV, NH, 1);
}

// round 6
// speedup vs baseline: 2.2582x; 1.0435x over previous
#include <cuda_runtime.h>
#include <cuda_fp16.h>
#include <cstdint>
#include <math.h>

// Problem constants
#define NB 64
#define NSX 128
#define NT 128
#define NE 128
#define NH 256
#define NV 32000
#define G4 1024

// ---------------- device scratch ----------------
__device__ float  g_xg[8192 * G4];          // x-gates fp32 (32 MB)
__device__ __half g_xh[8192 * NE];          // fp16 embedded inputs
__device__ __half g_yh[8192 * NH];          // fp16 layer outputs
__device__ float  g_hF[2 * NB * NH];
__device__ float  g_cF[2 * NB * NH];
__device__ __half g_w0[G4 * NE];            // enc Wih0 fp16
__device__ __half g_w1[G4 * NH];            // enc Wih1
__device__ __half g_w2[G4 * NE];            // dec Wih0
__device__ __half g_w3[G4 * NH];            // dec Wih1
__device__ __half g_fw[NV * NH];            // fc_W fp16

// ---------------- small helpers ----------------
__device__ __forceinline__ uint32_t smem_u32(const void* p) {
    uint32_t a;
    asm("{ .reg .u64 t; cvta.to.shared.u64 t, %1; cvt.u32.u64 %0, t; }"
        : "=r"(a) : "l"(p));
    return a;
}
__device__ __forceinline__ void cp16(uint32_t dst, const void* src) {
    asm volatile("cp.async.cg.shared.global [%0], [%1], 16;" :: "r"(dst), "l"(src));
}
__device__ __forceinline__ void ldsm4(uint32_t& r0, uint32_t& r1, uint32_t& r2,
                                      uint32_t& r3, uint32_t addr) {
    asm volatile("ldmatrix.sync.aligned.m8n8.x4.shared.b16 {%0,%1,%2,%3}, [%4];"
                 : "=r"(r0), "=r"(r1), "=r"(r2), "=r"(r3) : "r"(addr));
}
__device__ __forceinline__ void mma16816(float* c, const uint32_t* a,
                                         uint32_t b0, uint32_t b1) {
    asm volatile(
        "mma.sync.aligned.m16n8k16.row.col.f32.f16.f16.f32 "
        "{%0,%1,%2,%3}, {%4,%5,%6,%7}, {%8,%9}, {%0,%1,%2,%3};"
        : "+f"(c[0]), "+f"(c[1]), "+f"(c[2]), "+f"(c[3])
        : "r"(a[0]), "r"(a[1]), "r"(a[2]), "r"(a[3]), "r"(b0), "r"(b1));
}
#define CLUSTER_SYNC() do { \
    asm volatile("barrier.cluster.arrive.aligned;" ::: "memory"); \
    asm volatile("barrier.cluster.wait.aligned;" ::: "memory"); \
} while (0)

// ---------------- conversion / embedding kernels ----------------
__global__ void f2h_kernel(const float* __restrict__ s, __half* __restrict__ d, int n) {
    int i = blockIdx.x * blockDim.x + threadIdx.x;
    if (i < n) d[i] = __float2half(s[i]);
}

__global__ void embed_src_kernel(const int* __restrict__ src,
                                 const float* __restrict__ emb,
                                 __half* __restrict__ out) {
    int idx = blockIdx.x * blockDim.x + threadIdx.x;
    if (idx >= NSX * NB * NE) return;
    int e = idx % NE;
    int r = idx / NE;
    int b = r % NB;
    int s = r / NB;
    out[(size_t)r * NE + e] = __float2half(emb[(size_t)src[b * NSX + s] * NE + e]);
}

__global__ void embed_trg_kernel(const int* __restrict__ trg,
                                 const float* __restrict__ emb,
                                 __half* __restrict__ out) {
    int idx = blockIdx.x * blockDim.x + threadIdx.x;
    if (idx >= 127 * NB * NE) return;
    int e = idx % NE;
    int r = idx / NE;
    int b = r % NB;
    int t = r / NB;
    int tok = (t == 0) ? 1 : trg[b * NT + t];
    out[(size_t)r * NE + e] = __float2half(emb[(size_t)tok * NE + e]);
}

__global__ void zero_first_kernel(float* __restrict__ out) {
    int idx = blockIdx.x * blockDim.x + threadIdx.x;
    if (idx >= NB * NV) return;
    int v = idx % NV;
    int b = idx / NV;
    out[(size_t)b * NT * NV + v] = 0.f;
}

// ---------------- fp16 tensor-core GEMM (wide warp tiles) ----------------
// Block tile 128(M) x 256(N), BK=64, warp tile 64x64 (8 warps = 2x4).
// C[m,n] = sum_k A[m,k]*W[n,k] + b0[n] (+b1[n]).
// fcMode: logical row m = t*64+b -> C[(b*128 + t + 1)*NV + n], skip m >= 8128.
#define GSTAGE 49152                  // A 16KB + B 32KB
#define GSMEM  (3 * GSTAGE)

__global__ void __launch_bounds__(256, 1)
gemm16_kernel(const __half* __restrict__ A, const __half* __restrict__ W,
              const float* __restrict__ b0, const float* __restrict__ b1,
              float* __restrict__ C, int N, int K, int fcMode) {
    extern __shared__ char smbuf[];
    const uint32_t sb = smem_u32(smbuf);
    const int tid = threadIdx.x;
    const int lane = tid & 31;
    const int wid = tid >> 5;
    const int warp_m = wid & 1;       // 2 warps over M (64 rows each)
    const int warp_n = wid >> 1;      // 4 warps over N (64 cols each)
    const int m0 = blockIdx.y * 128;
    const int n0 = blockIdx.x * 256;
    const int KT = K >> 6;            // 2 or 4

    float acc[4][8][4];
#pragma unroll
    for (int i = 0; i < 4; i++)
#pragma unroll
        for (int j = 0; j < 8; j++)
#pragma unroll
            for (int q = 0; q < 4; q++) acc[i][j][q] = 0.f;

    auto loadStage = [&](int kt, int s) {
        const uint32_t st = sb + (uint32_t)s * GSTAGE;
        const __half* Ag = A + (size_t)m0 * K + kt * 64;
        const __half* Wg = W + (size_t)n0 * K + kt * 64;
#pragma unroll
        for (int i = 0; i < 4; i++) {            // A: 1024 16B-chunks
            int idx = i * 256 + tid;
            int row = idx >> 3, c = idx & 7;
            uint32_t off = (uint32_t)(row * 128 + ((c ^ (row & 7)) << 4));
            cp16(st + off, Ag + (size_t)row * K + c * 8);
        }
#pragma unroll
        for (int i = 0; i < 8; i++) {            // B: 2048 16B-chunks
            int idx = i * 256 + tid;
            int row = idx >> 3, c = idx & 7;
            uint32_t off = (uint32_t)(row * 128 + ((c ^ (row & 7)) << 4));
            cp16(st + 16384 + off, Wg + (size_t)row * K + c * 8);
        }
        asm volatile("cp.async.commit_group;" ::: "memory");
    };

    loadStage(0, 0);
    loadStage(1, 1);
    asm volatile("cp.async.wait_group 1;" ::: "memory");
    __syncthreads();

    for (int kt = 0; kt < KT; kt++) {
        const int s = kt % 3;
        if (kt + 2 < KT) loadStage(kt + 2, (kt + 2) % 3);
        const uint32_t stA = sb + (uint32_t)s * GSTAGE;
        const uint32_t stB = stA + 16384;
#pragma unroll
        for (int k16 = 0; k16 < 4; k16++) {
            uint32_t a[4][4];
#pragma unroll
            for (int mt = 0; mt < 4; mt++) {
                int row = warp_m * 64 + mt * 16 + (lane & 15);
                int ch = k16 * 2 + (lane >> 4);
                ldsm4(a[mt][0], a[mt][1], a[mt][2], a[mt][3],
                      stA + row * 128 + ((ch ^ (row & 7)) << 4));
            }
#pragma unroll
            for (int p = 0; p < 4; p++) {
                int nrow = warp_n * 64 + p * 16 + ((lane >> 4) & 1) * 8 + (lane & 7);
                int ch = k16 * 2 + ((lane >> 3) & 1);
                uint32_t br0, br1, br2, br3;
                ldsm4(br0, br1, br2, br3,
                      stB + nrow * 128 + ((ch ^ (nrow & 7)) << 4));
#pragma unroll
                for (int mt = 0; mt < 4; mt++) {
                    mma16816(acc[mt][2 * p],     a[mt], br0, br1);
                    mma16816(acc[mt][2 * p + 1], a[mt], br2, br3);
                }
            }
        }
        asm volatile("cp.async.wait_group 1;" ::: "memory");
        __syncthreads();
    }

    // ---- epilogue ----
    const int lrow = lane >> 2;
    const int lcol = (lane & 3) * 2;
#pragma unroll
    for (int nt = 0; nt < 8; nt++) {
        const int n = n0 + warp_n * 64 + nt * 8 + lcol;
        float bv0 = b0 ? b0[n] : 0.f;
        float bv1 = b0 ? b0[n + 1] : 0.f;
        if (b1) { bv0 += b1[n]; bv1 += b1[n + 1]; }
#pragma unroll
        for (int mt = 0; mt < 4; mt++) {
            const int mbase = m0 + warp_m * 64 + mt * 16 + lrow;
#pragma unroll
            for (int half = 0; half < 2; half++) {
                const int m = mbase + half * 8;
                float2 v;
                v.x = acc[mt][nt][half * 2 + 0] + bv0;
                v.y = acc[mt][nt][half * 2 + 1] + bv1;
                if (fcMode) {
                    if (m < 8128) {
                        int t = m >> 6, b = m & 63;
                        *(float2*)(C + ((size_t)(b * 128 + t + 1)) * NV + n) = v;
                    }
                } else {
                    *(float2*)(C + (size_t)m * N + n) = v;
                }
            }
        }
    }
}

// ---------------- clustered persistent LSTM recurrence ----------------
#define REC_SMEM_FLOATS (256 * 129 + 2 * 1024 + 8 * 32 * 17)
#define REC_SMEM_BYTES  (REC_SMEM_FLOATS * 4)

__global__ void __cluster_dims__(8, 1, 1) __launch_bounds__(256, 1)
lstm_rec_kernel(const float* __restrict__ xg,
                const float* __restrict__ Whh,
                const float* __restrict__ hInit,
                const float* __restrict__ cInit,
                __half* __restrict__ ysh,
                float* __restrict__ hFin,
                float* __restrict__ cFin,
                int nSteps) {
    extern __shared__ float smf[];
    float* Wsl = smf;                      // 256*129
    float* hs0 = Wsl + 256 * 129;          // 1024 (buffer 0)
    float* hs1 = hs0 + 1024;               // 1024 (buffer 1)
    float* red = hs1 + 1024;               // 256*17

    const int tid = threadIdx.x;
    uint32_t rank;
    asm("mov.u32 %0, %%cluster_ctarank;" : "=r"(rank));
    const int bt = blockIdx.x >> 3;
    const int n0 = (int)rank * 32;
    const int ks = tid >> 5;
    const int nl = tid & 31;

    for (int j = 0; j < 128; j++) {
        Wsl[tid * 129 + j] =
            Whh[(size_t)((j >> 5) * 256 + n0 + (j & 31)) * 256 + tid];
    }

    const int fb = tid >> 5;
    const int fn = tid & 31;
    const int bG = bt * 4 + fb;
    float cS = 0.f;
    if (tid < 128 && cInit) cS = cInit[bG * 256 + n0 + fn];

    if (hInit)
        ((float4*)hs0)[tid] = ((const float4*)(hInit + (size_t)bt * 4 * 256))[tid];
    else
        ((float4*)hs0)[tid] = make_float4(0.f, 0.f, 0.f, 0.f);

    uint32_t remA[8], remB[8];
    if (tid < 128) {
        uint32_t offs = (uint32_t)(fb * 256 + n0 + fn) * 4;
        uint32_t la = smem_u32(hs0) + offs;
        uint32_t lb = smem_u32(hs1) + offs;
#pragma unroll
        for (int r = 0; r < 8; r++) {
            asm("mapa.shared::cluster.u32 %0, %1, %2;" : "=r"(remA[r]) : "r"(la), "r"(r));
            asm("mapa.shared::cluster.u32 %0, %1, %2;" : "=r"(remB[r]) : "r"(lb), "r"(r));
        }
    }
    __syncthreads();
    CLUSTER_SYNC();

    int p = 0;
    for (int step = 0; step < nSteps; step++) {
        const float* hcur = p ? hs1 : hs0;

        float part[4][4];
#pragma unroll
        for (int b = 0; b < 4; b++)
#pragma unroll
            for (int g = 0; g < 4; g++) part[b][g] = 0.f;

        const int k0 = ks * 32;
#pragma unroll 8
        for (int kk = 0; kk < 32; kk++) {
            const int k = k0 + kk;
            const float* w = Wsl + k * 129 + nl;
            float w0 = w[0], w1 = w[32], w2 = w[64], w3 = w[96];
#pragma unroll
            for (int b = 0; b < 4; b++) {
                float hv = hcur[b * 256 + k];
                part[b][0] += hv * w0;
                part[b][1] += hv * w1;
                part[b][2] += hv * w2;
                part[b][3] += hv * w3;
            }
        }
        {
            float* rp = red + tid * 17;
#pragma unroll
            for (int b = 0; b < 4; b++)
#pragma unroll
                for (int g = 0; g < 4; g++) rp[b * 4 + g] = part[b][g];
        }
        __syncthreads();

        if (tid < 128) {
            size_t row = (size_t)step * 64 + bG;
            const float* xr = xg + row * 1024 + n0 + fn;
            float gi = xr[0], gf = xr[256], gg = xr[512], go = xr[768];
#pragma unroll
            for (int q = 0; q < 8; q++) {
                const float* rq = red + (q * 32 + fn) * 17 + fb * 4;
                gi += rq[0]; gf += rq[1]; gg += rq[2]; go += rq[3];
            }
            float iv = 1.f / (1.f + expf(-gi));
            float fv = 1.f / (1.f + expf(-gf));
            float gv = tanhf(gg);
            float ov = 1.f / (1.f + expf(-go));
            cS = fv * cS + iv * gv;
            float h = ov * tanhf(cS);

            uint32_t hb = __float_as_uint(h);
#pragma unroll
            for (int r = 0; r < 8; r++) {
                uint32_t ra = p ? remA[r] : remB[r];
                asm volatile("st.shared::cluster.u32 [%0], %1;" :: "r"(ra), "r"(hb));
            }
            if (ysh) ysh[row * 256 + n0 + fn] = __float2half(h);
            if (step == nSteps - 1) {
                if (hFin) hFin[bG * 256 + n0 + fn] = h;
                if (cFin) cFin[bG * 256 + n0 + fn] = cS;
            }
        }

        CLUSTER_SYNC();
        p ^= 1;
    }
}

// ---------------- host launch ----------------
extern "C" void kernel_launch(void* const* d_in, const int* in_sizes, int n_in,
                              void* d_out, int out_size) {
    const int*   src     = (const int*)d_in[0];
    const int*   trg     = (const int*)d_in[1];
    const float* enc_emb = (const float*)d_in[2];
    const float* dec_emb = (const float*)d_in[3];
    const float* eWih0 = (const float*)d_in[4],  *eWhh0 = (const float*)d_in[5];
    const float* ebih0 = (const float*)d_in[6],  *ebhh0 = (const float*)d_in[7];
    const float* eWih1 = (const float*)d_in[8],  *eWhh1 = (const float*)d_in[9];
    const float* ebih1 = (const float*)d_in[10], *ebhh1 = (const float*)d_in[11];
    const float* dWih0 = (const float*)d_in[12], *dWhh0 = (const float*)d_in[13];
    const float* dbih0 = (const float*)d_in[14], *dbhh0 = (const float*)d_in[15];
    const float* dWih1 = (const float*)d_in[16], *dWhh1 = (const float*)d_in[17];
    const float* dbih1 = (const float*)d_in[18], *dbhh1 = (const float*)d_in[19];
    const float* fcW   = (const float*)d_in[20], *fcb   = (const float*)d_in[21];
    float* out = (float*)d_out;

    float *pxg, *phF, *pcF;
    __half *pxh, *pyh, *pw0, *pw1, *pw2, *pw3, *pfw;
    cudaGetSymbolAddress((void**)&pxg,   g_xg);
    cudaGetSymbolAddress((void**)&phF,   g_hF);
    cudaGetSymbolAddress((void**)&pcF,   g_cF);
    cudaGetSymbolAddress((void**)&pxh,   g_xh);
    cudaGetSymbolAddress((void**)&pyh,   g_yh);
    cudaGetSymbolAddress((void**)&pw0,   g_w0);
    cudaGetSymbolAddress((void**)&pw1,   g_w1);
    cudaGetSymbolAddress((void**)&pw2,   g_w2);
    cudaGetSymbolAddress((void**)&pw3,   g_w3);
    cudaGetSymbolAddress((void**)&pfw,   g_fw);

    cudaFuncSetAttribute(lstm_rec_kernel,
                         cudaFuncAttributeMaxDynamicSharedMemorySize, REC_SMEM_BYTES);
    cudaFuncSetAttribute(gemm16_kernel,
                         cudaFuncAttributeMaxDynamicSharedMemorySize, GSMEM);

    // weight conversions (front-loaded)
    f2h_kernel<<<(G4 * NE + 255) / 256, 256>>>(eWih0, pw0, G4 * NE);
    f2h_kernel<<<(G4 * NH + 255) / 256, 256>>>(eWih1, pw1, G4 * NH);
    f2h_kernel<<<(G4 * NE + 255) / 256, 256>>>(dWih0, pw2, G4 * NE);
    f2h_kernel<<<(G4 * NH + 255) / 256, 256>>>(dWih1, pw3, G4 * NH);
    f2h_kernel<<<(NV * NH + 255) / 256, 256>>>(fcW, pfw, NV * NH);

    // ---- Encoder ----
    embed_src_kernel<<<(NSX * NB * NE + 255) / 256, 256>>>(src, enc_emb, pxh);
    gemm16_kernel<<<dim3(4, 64), 256, GSMEM>>>(pxh, pw0, ebih0, ebhh0, pxg,
                                               G4, NE, 0);
    lstm_rec_kernel<<<128, 256, REC_SMEM_BYTES>>>(pxg, eWhh0, nullptr, nullptr,
                                                  pyh, phF, pcF, 128);
    gemm16_kernel<<<dim3(4, 64), 256, GSMEM>>>(pyh, pw1, ebih1, ebhh1, pxg,
                                               G4, NH, 0);
    lstm_rec_kernel<<<128, 256, REC_SMEM_BYTES>>>(pxg, eWhh1, nullptr, nullptr,
                                                  nullptr, phF + NB * NH, pcF + NB * NH,
                                                  128);

    // ---- Decoder (teacher forced) ----
    embed_trg_kernel<<<(127 * NB * NE + 255) / 256, 256>>>(trg, dec_emb, pxh);
    gemm16_kernel<<<dim3(4, 64), 256, GSMEM>>>(pxh, pw2, dbih0, dbhh0, pxg,
                                               G4, NE, 0);
    lstm_rec_kernel<<<128, 256, REC_SMEM_BYTES>>>(pxg, dWhh0, phF, pcF,
                                                  pyh, nullptr, nullptr, 127);
    gemm16_kernel<<<dim3(4, 64), 256, GSMEM>>>(pyh, pw3, dbih1, dbhh1, pxg,
                                               G4, NH, 0);
    lstm_rec_kernel<<<128, 256, REC_SMEM_BYTES>>>(pxg, dWhh1, phF + NB * NH, pcF + NB * NH,
                                                  pyh, nullptr, nullptr, 127);

    // ---- Output: fp16 tensor-core FC over all steps ----
    zero_first_kernel<<<(NB * NV + 255) / 256, 256>>>(out);
    gemm16_kernel<<<dim3(125, 64), 256, GSMEM>>>(pyh, pfw, fcb, nullptr, out,
                                                 NV, NH, 1);
}